// round 11
// baseline (speedup 1.0000x reference)
#include <cuda_runtime.h>
#include <cuda_fp16.h>
#include <cstdint>
#include <cstddef>

// ============================================================================
// Problem constants
// ============================================================================
#define NT      8192            // n_test == n_train
#define NF      64              // n_feat
#define KD      384             // GEMM K = 64 feat * 3 Fourier dims * 2 (hi/lo)
#define BM      128             // CTA M tile
#define BN      128             // CTA N tile
#define BK      64              // halfs per K chunk (128 bytes/row)
#define NCHUNK  (KD / BK)       // 6
#define NSTAGE  3

// SMEM: three stages of (A tile 16KB + B tile 16KB)
#define STAGE_BYTES (BM * 128 + BN * 128)           // 32768
#define SM_A(s)     ((s) * STAGE_BYTES)
#define SM_B(s)     ((s) * STAGE_BYTES + BM * 128)
#define SMEM_TOTAL  (NSTAGE * STAGE_BYTES)          // 98304 (x2 CTAs = 192KB/SM)

// ============================================================================
// Device scratch (no allocations allowed)
// ============================================================================
__device__ __align__(1024) __half g_A[(size_t)NT * KD];   // 6 MB Fourier pack (test, weighted)
__device__ __align__(1024) __half g_B[(size_t)NT * KD];   // 6 MB Fourier pack (train)
__device__ unsigned g_rowmax[NT];                          // bits of (rowmax_log + 128)
__device__ float    g_base;                                // -64*ln3 + 0.25*sum(w)

// ============================================================================
// Helpers
// ============================================================================
__device__ __forceinline__ uint32_t smem_u32(const void* p) {
    uint32_t a;
    asm("{ .reg .u64 t; cvta.to.shared.u64 t, %1; cvt.u32.u64 %0, t; }"
        : "=r"(a) : "l"(p));
    return a;
}

__device__ __forceinline__ uint32_t sw128(uint32_t off) {
    return off ^ ((off >> 3) & 0x70u);
}

__device__ __forceinline__ void cp16(uint32_t smem_dst, const void* gmem_src) {
    asm volatile("cp.async.cg.shared.global [%0], [%1], 16;"
                 :: "r"(smem_dst), "l"(gmem_src) : "memory");
}

__device__ __forceinline__ void ldm4(uint32_t* r, uint32_t addr) {
    asm volatile("ldmatrix.sync.aligned.m8n8.x4.shared.b16 {%0,%1,%2,%3}, [%4];"
                 : "=r"(r[0]), "=r"(r[1]), "=r"(r[2]), "=r"(r[3]) : "r"(addr));
}

__device__ __forceinline__ void mma16816(float* d, const uint32_t* a, const uint32_t* b) {
    asm volatile(
        "mma.sync.aligned.m16n8k16.row.col.f32.f16.f16.f32 "
        "{%0,%1,%2,%3}, {%4,%5,%6,%7}, {%8,%9}, {%0,%1,%2,%3};"
        : "+f"(d[0]), "+f"(d[1]), "+f"(d[2]), "+f"(d[3])
        : "r"(a[0]), "r"(a[1]), "r"(a[2]), "r"(a[3]), "r"(b[0]), "r"(b[1]));
}

// sign-apply on fp16 bits: sgn in {-1,0,+1}
__device__ __forceinline__ unsigned short sgn16(unsigned short v, int sgn) {
    return sgn == 0 ? (unsigned short)0
                    : (sgn > 0 ? v : (unsigned short)(v ^ 0x8000u));
}

// ============================================================================
// Kernel 1: Fourier pack + rowmax reset + base reduction  (proven R6/R8)
// ============================================================================
__global__ __launch_bounds__(256) void pack_kernel(
    const float* __restrict__ bw,
    const float* __restrict__ testX,
    const float* __restrict__ trainX)
{
    int idx = blockIdx.x * 256 + threadIdx.x;     // 0 .. NT*NF-1
    if (idx < NT) g_rowmax[idx] = 0u;             // stored values always > 0

    __shared__ float sw[NF];
    if (blockIdx.x == 0) {
        if (threadIdx.x < NF) {
            float h = bw[threadIdx.x];
            sw[threadIdx.x] = logf(3.0f * (1.0f - h) / h);
        }
        __syncthreads();
        if (threadIdx.x == 0) {
            float s = 0.0f;
            #pragma unroll
            for (int f = 0; f < NF; f++) s += sw[f];
            g_base = -64.0f * 1.0986122886681098f + 0.25f * s;
        }
    }

    if (idx >= NT * NF) return;
    int i = idx >> 6;
    int f = idx & (NF - 1);

    float h = bw[f];
    float w = logf(3.0f * (1.0f - h) / h);        // log_true - log_false (> 0)
    float w2 = 0.5f * w, w4 = 0.25f * w;
    __half h2 = __float2half_rn(w2);
    unsigned short H2 = __half_as_ushort(h2);
    unsigned short L2 = __half_as_ushort(__float2half_rn(w2 - __half2float(h2)));
    __half h4 = __float2half_rn(w4);
    unsigned short H4 = __half_as_ushort(h4);
    unsigned short L4 = __half_as_ushort(__float2half_rn(w4 - __half2float(h4)));

    int t = (int)testX[idx];
    int s = (int)trainX[idx];

    int ct = (t == 0) ? 1 : ((t == 2) ? -1 : 0);
    int st = (t == 1) ? 1 : ((t == 3) ? -1 : 0);
    int pt = (t & 1) ? -1 : 1;
    int cs = (s == 0) ? 1 : ((s == 2) ? -1 : 0);
    int ss = (s == 1) ? 1 : ((s == 3) ? -1 : 0);
    int ps = (s & 1) ? -1 : 1;

    const unsigned short ONE = 0x3C00u;
    unsigned short a0 = sgn16(H2, ct), a1 = sgn16(L2, ct);
    unsigned short a2 = sgn16(H2, st), a3 = sgn16(L2, st);
    unsigned short a4 = sgn16(H4, pt), a5 = sgn16(L4, pt);
    unsigned short bc = sgn16(ONE, cs), bs = sgn16(ONE, ss), bp = sgn16(ONE, ps);

    uint32_t* pa = reinterpret_cast<uint32_t*>(
        reinterpret_cast<char*>(g_A) + (size_t)i * (KD * 2) + f * 12);
    uint32_t* pb = reinterpret_cast<uint32_t*>(
        reinterpret_cast<char*>(g_B) + (size_t)i * (KD * 2) + f * 12);
    pa[0] = (uint32_t)a0 | ((uint32_t)a1 << 16);
    pa[1] = (uint32_t)a2 | ((uint32_t)a3 << 16);
    pa[2] = (uint32_t)a4 | ((uint32_t)a5 << 16);
    pb[0] = (uint32_t)bc | ((uint32_t)bc << 16);
    pb[1] = (uint32_t)bs | ((uint32_t)bs << 16);
    pb[2] = (uint32_t)bp | ((uint32_t)bp << 16);
}

// ============================================================================
// Kernel 2: HMMA GEMM  log_dist = A @ B^T + base ; writes log_dist ; rowmax
//   R5 geometry: 128x128 CTA, 8 warps (4M x 2N, warp tile 32x64), 2 CTA/SM,
//   3-stage cp.async. Tile order strip-major: high strips written LAST.
// ============================================================================
__global__ __launch_bounds__(256, 2) void gemm_kernel(float* __restrict__ out)
{
    extern __shared__ __align__(1024) unsigned char smem[];
    const int tid  = threadIdx.x;
    const int wid  = tid >> 5;
    const int lane = tid & 31;
    const int wm   = wid >> 1;           // warp M index 0..3  (rows wm*32)
    const int wn   = wid & 1;            // warp N index 0..1  (cols wn*64)
    const int m0 = (blockIdx.x >> 6) * BM;    // strip-major: strips finish in order
    const int n0 = (blockIdx.x & 63) * BN;

    const uint32_t sbase = smem_u32(smem);
    const float BASEV = g_base;
    const __half* gA = g_A + (size_t)m0 * KD;
    const __half* gB = g_B + (size_t)n0 * KD;

    // ---- chunk loader: A 1024 + B 1024 16B units, 8 per thread ----
    #define LOAD_CHUNK(c, s)                                                    \
    do {                                                                        \
        uint32_t aB = sbase + SM_A(s), bB = sbase + SM_B(s);                    \
        _Pragma("unroll")                                                       \
        for (int i = 0; i < 8; i++) {                                           \
            int u = tid + i * 256;                                              \
            if (u < 1024) {                                                     \
                int row = u >> 3, seg = u & 7;                                  \
                cp16(aB + sw128(row * 128 + seg * 16),                          \
                     gA + (size_t)row * KD + (c) * BK + seg * 8);               \
            } else {                                                            \
                int u2 = u - 1024;                                              \
                int row = u2 >> 3, seg = u2 & 7;                                \
                cp16(bB + sw128(row * 128 + seg * 16),                          \
                     gB + (size_t)row * KD + (c) * BK + seg * 8);               \
            }                                                                   \
        }                                                                       \
        asm volatile("cp.async.commit_group;");                                 \
    } while (0)

    // ---- per-lane ldmatrix geometry (proven R5) ----
    const int aRow   = wm * 32 + ((lane >> 3) & 1) * 8 + (lane & 7);
    const int aKhalf = (lane >> 4) & 1;
    const int arow7  = aRow & 7;
    const int bRowIn = ((lane >> 4) & 1) * 8 + (lane & 7);
    const int bKhalf = (lane >> 3) & 1;
    const int brow7  = bRowIn & 7;

    float acc[2][8][4];
    #pragma unroll
    for (int t = 0; t < 2; t++)
        #pragma unroll
        for (int j = 0; j < 8; j++)
            #pragma unroll
            for (int v = 0; v < 4; v++) acc[t][j][v] = 0.0f;

    LOAD_CHUNK(0, 0);
    LOAD_CHUNK(1, 1);

    for (int c = 0; c < NCHUNK; c++) {
        if (c + 2 < NCHUNK) {
            __syncthreads();                       // stage (c+2)%3 free to overwrite
            LOAD_CHUNK(c + 2, (c + 2) % NSTAGE);
            asm volatile("cp.async.wait_group 2;");
        } else if (c + 1 < NCHUNK) {
            asm volatile("cp.async.wait_group 1;");
        } else {
            asm volatile("cp.async.wait_group 0;");
        }
        __syncthreads();

        const uint32_t aBse = sbase + SM_A(c % NSTAGE);
        const uint32_t bBse = sbase + SM_B(c % NSTAGE);

        #pragma unroll
        for (int ks = 0; ks < 4; ks++) {           // 4 k16 steps per 64-half chunk
            uint32_t afr[2][4], bfr[4][4];
            #pragma unroll
            for (int t = 0; t < 2; t++) {
                uint32_t addr = aBse + (uint32_t)(aRow + t * 16) * 128
                              + (uint32_t)(((ks * 2 + aKhalf) ^ arow7) * 16);
                ldm4(afr[t], addr);
            }
            #pragma unroll
            for (int nt = 0; nt < 4; nt++) {
                uint32_t row = (uint32_t)(wn * 64 + nt * 16 + bRowIn);
                uint32_t addr = bBse + row * 128
                              + (uint32_t)(((ks * 2 + bKhalf) ^ brow7) * 16);
                ldm4(bfr[nt], addr);
            }
            #pragma unroll
            for (int t = 0; t < 2; t++)
                #pragma unroll
                for (int nt = 0; nt < 4; nt++) {
                    mma16816(acc[t][nt * 2],     afr[t], &bfr[nt][0]);
                    mma16816(acc[t][nt * 2 + 1], afr[t], &bfr[nt][2]);
                }
        }
    }

    // ---- epilogue: add base, write log_dist, per-row max ----
    const int g = lane >> 2;
    const int q = lane & 3;
    #pragma unroll
    for (int t = 0; t < 2; t++) {
        const int r0 = m0 + wm * 32 + t * 16 + g;
        const int r1 = r0 + 8;
        float mx0 = -1e30f, mx1 = -1e30f;
        #pragma unroll
        for (int j = 0; j < 8; j++) {
            float v0 = acc[t][j][0] + BASEV;
            float v1 = acc[t][j][1] + BASEV;
            float v2 = acc[t][j][2] + BASEV;
            float v3 = acc[t][j][3] + BASEV;
            const int col = n0 + wn * 64 + j * 8 + q * 2;
            *reinterpret_cast<float2*>(out + (size_t)r0 * NT + col) = make_float2(v0, v1);
            *reinterpret_cast<float2*>(out + (size_t)r1 * NT + col) = make_float2(v2, v3);
            mx0 = fmaxf(mx0, fmaxf(v0, v1));
            mx1 = fmaxf(mx1, fmaxf(v2, v3));
        }
        mx0 = fmaxf(mx0, __shfl_xor_sync(0xffffffffu, mx0, 1));
        mx0 = fmaxf(mx0, __shfl_xor_sync(0xffffffffu, mx0, 2));
        mx1 = fmaxf(mx1, __shfl_xor_sync(0xffffffffu, mx1, 1));
        mx1 = fmaxf(mx1, __shfl_xor_sync(0xffffffffu, mx1, 2));
        if (q == 0) {
            atomicMax(&g_rowmax[r0], __float_as_uint(mx0 + 128.0f));
            atomicMax(&g_rowmax[r1], __float_as_uint(mx1 + 128.0f));
        }
    }
}

// ============================================================================
// Kernel 3: out[i,j] = m_i * exp(log_dist[i,j] - m_i)
//   Reversed block order: start with the rows the GEMM wrote LAST (L2-hot).
// ============================================================================
#define FIN_BLOCKS ((int)(((size_t)NT * NT / 4) / 256))
__global__ __launch_bounds__(256) void finalize_kernel(float* __restrict__ out)
{
    int blk = FIN_BLOCKS - 1 - blockIdx.x;               // descending rows
    size_t i = (size_t)blk * 256 + threadIdx.x;          // over NT*NT/4 float4s
    float4* o4 = reinterpret_cast<float4*>(out);
    float4 v = o4[i];
    int row = (int)(i >> 11);                            // (i*4) / 8192
    float m = __uint_as_float(g_rowmax[row]) - 128.0f;
    v.x = m * expf(v.x - m);
    v.y = m * expf(v.y - m);
    v.z = m * expf(v.z - m);
    v.w = m * expf(v.w - m);
    o4[i] = v;
}

// ============================================================================
// Launch
// ============================================================================
extern "C" void kernel_launch(void* const* d_in, const int* in_sizes, int n_in,
                              void* d_out, int out_size)
{
    const float* bw = (const float*)d_in[0];
    const float* te = (const float*)d_in[1];
    const float* tr = (const float*)d_in[2];
    float* out = (float*)d_out;

    cudaFuncSetAttribute(gemm_kernel,
                         cudaFuncAttributeMaxDynamicSharedMemorySize, SMEM_TOTAL);

    pack_kernel<<<(NT * NF + 255) / 256, 256>>>(bw, te, tr);
    gemm_kernel<<<(NT / BM) * (NT / BN), 256, SMEM_TOTAL>>>(out);
    finalize_kernel<<<FIN_BLOCKS, 256>>>(out);
}

// round 12
// speedup vs baseline: 1.0309x; 1.0309x over previous
#include <cuda_runtime.h>
#include <cuda_fp16.h>
#include <cstdint>
#include <cstddef>

// ============================================================================
// Problem constants
// ============================================================================
#define NT      8192            // n_test == n_train
#define NF      64              // n_feat
#define KD      384             // GEMM K = 64 feat * 3 Fourier dims * 2 (hi/lo)
#define BM      128             // CTA M tile
#define BN      128             // CTA N tile
#define BK      64              // halfs per K chunk (128 bytes/row)
#define NCHUNK  (KD / BK)       // 6
#define NSTAGE  3

#define NSTRIP  (NT / BM)       // 64 row strips
#define NCOLT   (NT / BN)       // 64 col tiles per strip
#define NSTRIPW 4               // strips per wave
#define GRID    (NSTRIPW * NCOLT)   // 256 CTAs, all resident (2/SM proven in R8)
#define NWAVE   (NSTRIP / NSTRIPW)  // 16

// SMEM: three stages of (A tile 16KB + B tile 16KB)
#define STAGE_BYTES (BM * 128 + BN * 128)           // 32768
#define SM_A(s)     ((s) * STAGE_BYTES)
#define SM_B(s)     ((s) * STAGE_BYTES + BM * 128)
#define SMEM_TOTAL  (NSTAGE * STAGE_BYTES)          // 98304 (x2 CTAs = 192KB/SM)

// ============================================================================
// Device scratch (no allocations allowed)
// ============================================================================
__device__ __align__(1024) __half g_A[(size_t)NT * KD];   // 6 MB Fourier pack (test, weighted)
__device__ __align__(1024) __half g_B[(size_t)NT * KD];   // 6 MB Fourier pack (train)
__device__ unsigned g_rowmax[NT];                          // bits of (rowmax_log + 128)
__device__ float    g_base;                                // -64*ln3 + 0.25*sum(w)
__device__ int      g_done[NSTRIP];                        // completed tiles per strip

// ============================================================================
// Helpers
// ============================================================================
__device__ __forceinline__ uint32_t smem_u32(const void* p) {
    uint32_t a;
    asm("{ .reg .u64 t; cvta.to.shared.u64 t, %1; cvt.u32.u64 %0, t; }"
        : "=r"(a) : "l"(p));
    return a;
}

__device__ __forceinline__ uint32_t sw128(uint32_t off) {
    return off ^ ((off >> 3) & 0x70u);
}

__device__ __forceinline__ void cp16(uint32_t smem_dst, const void* gmem_src) {
    asm volatile("cp.async.cg.shared.global [%0], [%1], 16;"
                 :: "r"(smem_dst), "l"(gmem_src) : "memory");
}

__device__ __forceinline__ void ldm4(uint32_t* r, uint32_t addr) {
    asm volatile("ldmatrix.sync.aligned.m8n8.x4.shared.b16 {%0,%1,%2,%3}, [%4];"
                 : "=r"(r[0]), "=r"(r[1]), "=r"(r[2]), "=r"(r[3]) : "r"(addr));
}

__device__ __forceinline__ void mma16816(float* d, const uint32_t* a, const uint32_t* b) {
    asm volatile(
        "mma.sync.aligned.m16n8k16.row.col.f32.f16.f16.f32 "
        "{%0,%1,%2,%3}, {%4,%5,%6,%7}, {%8,%9}, {%0,%1,%2,%3};"
        : "+f"(d[0]), "+f"(d[1]), "+f"(d[2]), "+f"(d[3])
        : "r"(a[0]), "r"(a[1]), "r"(a[2]), "r"(a[3]), "r"(b[0]), "r"(b[1]));
}

// sign-apply on fp16 bits: sgn in {-1,0,+1}
__device__ __forceinline__ unsigned short sgn16(unsigned short v, int sgn) {
    return sgn == 0 ? (unsigned short)0
                    : (sgn > 0 ? v : (unsigned short)(v ^ 0x8000u));
}

// ============================================================================
// Kernel 1: Fourier pack + state reset + base reduction  (proven R6-R11)
// ============================================================================
__global__ __launch_bounds__(256) void pack_kernel(
    const float* __restrict__ bw,
    const float* __restrict__ testX,
    const float* __restrict__ trainX)
{
    int idx = blockIdx.x * 256 + threadIdx.x;     // 0 .. NT*NF-1
    if (idx < NT) g_rowmax[idx] = 0u;             // stored values always > 0
    if (idx < NSTRIP) g_done[idx] = 0;

    __shared__ float sw[NF];
    if (blockIdx.x == 0) {
        if (threadIdx.x < NF) {
            float h = bw[threadIdx.x];
            sw[threadIdx.x] = logf(3.0f * (1.0f - h) / h);
        }
        __syncthreads();
        if (threadIdx.x == 0) {
            float s = 0.0f;
            #pragma unroll
            for (int f = 0; f < NF; f++) s += sw[f];
            g_base = -64.0f * 1.0986122886681098f + 0.25f * s;
        }
    }

    if (idx >= NT * NF) return;
    int i = idx >> 6;
    int f = idx & (NF - 1);

    float h = bw[f];
    float w = logf(3.0f * (1.0f - h) / h);        // log_true - log_false (> 0)
    float w2 = 0.5f * w, w4 = 0.25f * w;
    __half h2 = __float2half_rn(w2);
    unsigned short H2 = __half_as_ushort(h2);
    unsigned short L2 = __half_as_ushort(__float2half_rn(w2 - __half2float(h2)));
    __half h4 = __float2half_rn(w4);
    unsigned short H4 = __half_as_ushort(h4);
    unsigned short L4 = __half_as_ushort(__float2half_rn(w4 - __half2float(h4)));

    int t = (int)testX[idx];
    int s = (int)trainX[idx];

    int ct = (t == 0) ? 1 : ((t == 2) ? -1 : 0);
    int st = (t == 1) ? 1 : ((t == 3) ? -1 : 0);
    int pt = (t & 1) ? -1 : 1;
    int cs = (s == 0) ? 1 : ((s == 2) ? -1 : 0);
    int ss = (s == 1) ? 1 : ((s == 3) ? -1 : 0);
    int ps = (s & 1) ? -1 : 1;

    const unsigned short ONE = 0x3C00u;
    unsigned short a0 = sgn16(H2, ct), a1 = sgn16(L2, ct);
    unsigned short a2 = sgn16(H2, st), a3 = sgn16(L2, st);
    unsigned short a4 = sgn16(H4, pt), a5 = sgn16(L4, pt);
    unsigned short bc = sgn16(ONE, cs), bs = sgn16(ONE, ss), bp = sgn16(ONE, ps);

    uint32_t* pa = reinterpret_cast<uint32_t*>(
        reinterpret_cast<char*>(g_A) + (size_t)i * (KD * 2) + f * 12);
    uint32_t* pb = reinterpret_cast<uint32_t*>(
        reinterpret_cast<char*>(g_B) + (size_t)i * (KD * 2) + f * 12);
    pa[0] = (uint32_t)a0 | ((uint32_t)a1 << 16);
    pa[1] = (uint32_t)a2 | ((uint32_t)a3 << 16);
    pa[2] = (uint32_t)a4 | ((uint32_t)a5 << 16);
    pb[0] = (uint32_t)bc | ((uint32_t)bc << 16);
    pb[1] = (uint32_t)bs | ((uint32_t)bs << 16);
    pb[2] = (uint32_t)bp | ((uint32_t)bp << 16);
}

// ============================================================================
// Kernel 2: single-pass wave-synchronized GEMM + exp epilogue
//   256 persistent CTAs = 16 waves x (4 strips x 64 col tiles).
//   Per wave: compute tile -> rowmax atomics -> strip barrier -> m*exp(x-m).
// ============================================================================
__global__ __launch_bounds__(256, 2) void gemm_fused_kernel(float* __restrict__ out)
{
    extern __shared__ __align__(1024) unsigned char smem[];
    __shared__ float s_rm[BM];
    const int tid  = threadIdx.x;
    const int wid  = tid >> 5;
    const int lane = tid & 31;
    const int wm   = wid >> 1;           // warp M index 0..3  (rows wm*32)
    const int wn   = wid & 1;            // warp N index 0..1  (cols wn*64)
    const int sIdx = blockIdx.x >> 6;    // strip-within-wave 0..3
    const int col  = blockIdx.x & 63;    // column tile (constant across waves)
    const int n0   = col * BN;

    const uint32_t sbase = smem_u32(smem);
    const float BASEV = g_base;
    const __half* gB = g_B + (size_t)n0 * KD;    // constant across waves

    #define LOAD_CHUNK(pA, pB, c, s)                                            \
    do {                                                                        \
        uint32_t aB = sbase + SM_A(s), bB = sbase + SM_B(s);                    \
        _Pragma("unroll")                                                       \
        for (int i = 0; i < 8; i++) {                                           \
            int u = tid + i * 256;                                              \
            if (u < 1024) {                                                     \
                int row = u >> 3, seg = u & 7;                                  \
                cp16(aB + sw128(row * 128 + seg * 16),                          \
                     (pA) + (size_t)row * KD + (c) * BK + seg * 8);             \
            } else {                                                            \
                int u2 = u - 1024;                                              \
                int row = u2 >> 3, seg = u2 & 7;                                \
                cp16(bB + sw128(row * 128 + seg * 16),                          \
                     (pB) + (size_t)row * KD + (c) * BK + seg * 8);             \
            }                                                                   \
        }                                                                       \
        asm volatile("cp.async.commit_group;");                                 \
    } while (0)

    // ---- per-lane ldmatrix geometry (proven R5/R11) ----
    const int aRow   = wm * 32 + ((lane >> 3) & 1) * 8 + (lane & 7);
    const int aKhalf = (lane >> 4) & 1;
    const int arow7  = aRow & 7;
    const int bRowIn = ((lane >> 4) & 1) * 8 + (lane & 7);
    const int bKhalf = (lane >> 3) & 1;
    const int brow7  = bRowIn & 7;
    const int g  = lane >> 2;
    const int q  = lane & 3;

    {   // prefetch wave 0 chunks 0,1
        const __half* gA0 = g_A + (size_t)(sIdx * BM) * KD;
        LOAD_CHUNK(gA0, gB, 0, 0);
        LOAD_CHUNK(gA0, gB, 1, 1);
    }

    for (int w = 0; w < NWAVE; w++) {
        const int strip = w * NSTRIPW + sIdx;
        const int m0 = strip * BM;
        const __half* gA = g_A + (size_t)m0 * KD;

        float acc[2][8][4];
        #pragma unroll
        for (int t = 0; t < 2; t++)
            #pragma unroll
            for (int j = 0; j < 8; j++)
                #pragma unroll
                for (int v = 0; v < 4; v++) acc[t][j][v] = 0.0f;

        for (int c = 0; c < NCHUNK; c++) {
            if (c + 2 < NCHUNK) {
                __syncthreads();                   // stage (c+2)%3 free to overwrite
                LOAD_CHUNK(gA, gB, c + 2, (c + 2) % NSTAGE);
                asm volatile("cp.async.wait_group 2;");
            } else if (c + 1 < NCHUNK) {
                asm volatile("cp.async.wait_group 1;");
            } else {
                asm volatile("cp.async.wait_group 0;");
            }
            __syncthreads();

            const uint32_t aBse = sbase + SM_A(c % NSTAGE);
            const uint32_t bBse = sbase + SM_B(c % NSTAGE);

            #pragma unroll
            for (int ks = 0; ks < 4; ks++) {       // 4 k16 steps per 64-half chunk
                uint32_t afr[2][4], bfr[4][4];
                #pragma unroll
                for (int t = 0; t < 2; t++) {
                    uint32_t addr = aBse + (uint32_t)(aRow + t * 16) * 128
                                  + (uint32_t)(((ks * 2 + aKhalf) ^ arow7) * 16);
                    ldm4(afr[t], addr);
                }
                #pragma unroll
                for (int nt = 0; nt < 4; nt++) {
                    uint32_t row = (uint32_t)(wn * 64 + nt * 16 + bRowIn);
                    uint32_t addr = bBse + row * 128
                                  + (uint32_t)(((ks * 2 + bKhalf) ^ brow7) * 16);
                    ldm4(bfr[nt], addr);
                }
                #pragma unroll
                for (int t = 0; t < 2; t++)
                    #pragma unroll
                    for (int nt = 0; nt < 4; nt++) {
                        mma16816(acc[t][nt * 2],     afr[t], &bfr[nt][0]);
                        mma16816(acc[t][nt * 2 + 1], afr[t], &bfr[nt][2]);
                    }
            }
        }

        // ---- prefetch next wave chunks 0,1 (stages 0,1 are consumed) ----
        // All warps have passed chunk 5's barrier, so chunks 3/4 reads of
        // stages 0/1 are complete; overwriting is safe without a barrier.
        if (w + 1 < NWAVE) {
            const __half* gAn = g_A + (size_t)((w + 1) * NSTRIPW + sIdx) * BM * KD;
            LOAD_CHUNK(gAn, gB, 0, 0);
            LOAD_CHUNK(gAn, gB, 1, 1);
        }

        // ---- rowmax: local max -> shfl -> atomicMax ----
        #pragma unroll
        for (int t = 0; t < 2; t++) {
            float mx0 = -1e30f, mx1 = -1e30f;
            #pragma unroll
            for (int j = 0; j < 8; j++) {
                mx0 = fmaxf(mx0, fmaxf(acc[t][j][0], acc[t][j][1]));
                mx1 = fmaxf(mx1, fmaxf(acc[t][j][2], acc[t][j][3]));
            }
            mx0 = fmaxf(mx0, __shfl_xor_sync(0xffffffffu, mx0, 1));
            mx0 = fmaxf(mx0, __shfl_xor_sync(0xffffffffu, mx0, 2));
            mx1 = fmaxf(mx1, __shfl_xor_sync(0xffffffffu, mx1, 1));
            mx1 = fmaxf(mx1, __shfl_xor_sync(0xffffffffu, mx1, 2));
            if (q == 0) {
                const int r0 = m0 + wm * 32 + t * 16 + g;
                atomicMax(&g_rowmax[r0],     __float_as_uint(mx0 + BASEV + 128.0f));
                atomicMax(&g_rowmax[r0 + 8], __float_as_uint(mx1 + BASEV + 128.0f));
            }
        }

        // ---- strip barrier: wait for all 64 tiles of this strip ----
        __threadfence();
        __syncthreads();
        if (tid == 0) {
            atomicAdd(&g_done[strip], 1);
            while (atomicAdd(&g_done[strip], 0) < NCOLT) { }
            __threadfence();
        }
        __syncthreads();

        // ---- load finalized row maxima into smem ----
        if (tid < BM) {
            unsigned bits = atomicOr(&g_rowmax[m0 + tid], 0u);
            s_rm[tid] = __uint_as_float(bits) - 128.0f;
        }
        __syncthreads();

        // ---- write out = m * exp(x - m), straight from registers ----
        #pragma unroll
        for (int t = 0; t < 2; t++) {
            const int lr0 = wm * 32 + t * 16 + g;
            const int lr1 = lr0 + 8;
            const float m0v = s_rm[lr0];
            const float m1v = s_rm[lr1];
            float* orow0 = out + (size_t)(m0 + lr0) * NT + n0;
            float* orow1 = out + (size_t)(m0 + lr1) * NT + n0;
            #pragma unroll
            for (int j = 0; j < 8; j++) {
                float v0 = acc[t][j][0] + BASEV;
                float v1 = acc[t][j][1] + BASEV;
                float v2 = acc[t][j][2] + BASEV;
                float v3 = acc[t][j][3] + BASEV;
                const int c2 = wn * 64 + j * 8 + q * 2;
                *reinterpret_cast<float2*>(orow0 + c2) =
                    make_float2(m0v * __expf(v0 - m0v), m0v * __expf(v1 - m0v));
                *reinterpret_cast<float2*>(orow1 + c2) =
                    make_float2(m1v * __expf(v2 - m1v), m1v * __expf(v3 - m1v));
            }
        }
        __syncthreads();    // s_rm reuse safe next wave
    }
}

// ============================================================================
// Launch
// ============================================================================
extern "C" void kernel_launch(void* const* d_in, const int* in_sizes, int n_in,
                              void* d_out, int out_size)
{
    const float* bw = (const float*)d_in[0];
    const float* te = (const float*)d_in[1];
    const float* tr = (const float*)d_in[2];
    float* out = (float*)d_out;

    cudaFuncSetAttribute(gemm_fused_kernel,
                         cudaFuncAttributeMaxDynamicSharedMemorySize, SMEM_TOTAL);

    pack_kernel<<<(NT * NF + 255) / 256, 256>>>(bw, te, tr);
    gemm_fused_kernel<<<GRID, 256, SMEM_TOTAL>>>(out);
}